// round 2
// baseline (speedup 1.0000x reference)
#include <cuda_runtime.h>
#include <math.h>

#define NB 8
#define NC 512
#define HIN 32
#define HT 65
#define HO 64

// ---------------- scratch (device globals; no allocations allowed) ----------
__device__ float g_xs[NB * NC * HIN * HIN];   // style-scaled input (16.8 MB)
__device__ float g_t1[NB * NC * HT * HT];     // conv1 (transpose) output 65x65 (69 MB)
__device__ float g_a1[NB * NC * HO * HO];     // blur+noise+lrelu, pre-scaled by s2 (67 MB)
__device__ float g_a2[NB * NC * HO * HO];     // conv2 output, pre-scaled by s_rgb (67 MB)
__device__ float g_d1[NB * NC];
__device__ float g_d2[NB * NC];

struct TapList { int dy[9]; int dx[9]; int wo[9]; };

// ---------------- K0: demodulation factors ----------------------------------
// d[b,co] = scale * rsqrt(scale^2 * sum_{ci,kk} (w[co,ci,kk]*s[b,ci])^2 + 1e-8)
__global__ void k_demod(const float* __restrict__ w, const float* __restrict__ s,
                        float* __restrict__ d, float scale) {
    int b  = blockIdx.x >> 9;
    int co = blockIdx.x & 511;
    const float* wr = w + co * 4608;
    const float* sr = s + b * 512;
    float acc = 0.f;
    for (int k = threadIdx.x; k < 4608; k += 128) {
        int ci = k / 9;
        float t = wr[k] * sr[ci];
        acc += t * t;
    }
    __shared__ float red[128];
    red[threadIdx.x] = acc;
    __syncthreads();
    for (int off = 64; off > 0; off >>= 1) {
        if (threadIdx.x < off) red[threadIdx.x] += red[threadIdx.x + off];
        __syncthreads();
    }
    if (threadIdx.x == 0)
        d[b * 512 + co] = scale * rsqrtf(scale * scale * red[0] + 1e-8f);
}

// ---------------- K_scale: xs = x * s1[b,c] ---------------------------------
__global__ void k_scale_x(const float* __restrict__ x, const float* __restrict__ s1,
                          float* __restrict__ xs) {
    int i = blockIdx.x * 256 + threadIdx.x;
    if (i < NB * NC * HIN * HIN) {
        int c = (i >> 10) & 511;   // /1024 % 512
        int b = i >> 19;           // /(512*1024)
        xs[i] = x[i] * s1[b * 512 + c];
    }
}

// ---------------- implicit-GEMM conv -----------------------------------------
// M=512(cout) x N=GH*GW(pixels) x K=512*NTAPS. 128x128x16 tiles, 8x8/thread.
// EPI 0: out = acc * dmod   (conv1 phases -> strided write into 65x65 buffer)
// EPI 1: out = lrelu(acc*dmod + nw*noise + bias)*sqrt2 * snext  (conv2)
template <int NTAPS, int EPI>
__global__ __launch_bounds__(256, 2) void conv_gemm(
    const float* __restrict__ in, const float* __restrict__ wgt,
    float* __restrict__ out,
    const float* __restrict__ dmod,
    const float* __restrict__ noise, const float* __restrict__ nwp,
    const float* __restrict__ bias, const float* __restrict__ snext,
    int IH, int IW, int GH, int GW,
    int out_bstride, int out_cstride, int out_ys, int out_xs, int out_off,
    TapList taps)
{
    const int BM = 128, BN = 128, BK = 16;
    const int LDA = BM + 4, LDB = BN + 4;
    __shared__ float As[BK * LDA];
    __shared__ float Bs[BK * LDB];

    int tid = threadIdx.x;
    int b   = blockIdx.z;
    int co0 = blockIdx.y * BM;
    int n0  = blockIdx.x * BN;
    int GHW = GH * GW;
    int K   = 512 * NTAPS;

    const float* inb = in + (size_t)b * 512 * IH * IW;

    // per-thread fixed pixel coords for the 8 B-tile elements it loads each step
    int boy[8], box[8];
#pragma unroll
    for (int l = 0; l < 8; l++) {
        int idx = tid + l * 256;
        int nl  = idx & 127;
        int ng  = n0 + nl;
        if (ng < GHW) {
            int y = ng / GW;
            boy[l] = y;
            box[l] = ng - y * GW;
        } else {
            boy[l] = -100000;  // sentinel -> always out of bounds
            box[l] = 0;
        }
    }

    float acc[8][8];
#pragma unroll
    for (int i = 0; i < 8; i++)
#pragma unroll
        for (int j = 0; j < 8; j++) acc[i][j] = 0.f;

    int ty = tid >> 4, tx = tid & 15;
    int ty8 = ty * 8, tx8 = tx * 8;

    for (int kb = 0; kb < K; kb += BK) {
        // --- load A tile: w[co0+col][ci*9 + wo[t]] , k-fast coalesced LDG ---
#pragma unroll
        for (int l = 0; l < 8; l++) {
            int idx = tid + l * 256;
            int kl  = idx & 15;
            int col = idx >> 4;
            int kg  = kb + kl;
            int ci  = kg / NTAPS;
            int t   = kg - ci * NTAPS;
            As[kl * LDA + col] = wgt[(size_t)(co0 + col) * 4608 + ci * 9 + taps.wo[t]];
        }
        // --- load B tile: gathered/predicated input ---
#pragma unroll
        for (int l = 0; l < 8; l++) {
            int idx = tid + l * 256;
            int nl  = idx & 127;
            int kl  = idx >> 7;
            int kg  = kb + kl;
            int ci  = kg / NTAPS;
            int t   = kg - ci * NTAPS;
            int iy  = boy[l] + taps.dy[t];
            int ix  = box[l] + taps.dx[t];
            float v = 0.f;
            if (iy >= 0 && iy < IH && ix >= 0 && ix < IW)
                v = inb[(size_t)(ci * IH + iy) * IW + ix];
            Bs[kl * LDB + nl] = v;
        }
        __syncthreads();

#pragma unroll
        for (int kk = 0; kk < BK; kk++) {
            const float4* Ap = reinterpret_cast<const float4*>(&As[kk * LDA + ty8]);
            const float4* Bp = reinterpret_cast<const float4*>(&Bs[kk * LDB + tx8]);
            float4 a0 = Ap[0], a1 = Ap[1];
            float4 b0 = Bp[0], b1 = Bp[1];
            float av[8] = {a0.x, a0.y, a0.z, a0.w, a1.x, a1.y, a1.z, a1.w};
            float bv[8] = {b0.x, b0.y, b0.z, b0.w, b1.x, b1.y, b1.z, b1.w};
#pragma unroll
            for (int i = 0; i < 8; i++)
#pragma unroll
                for (int j = 0; j < 8; j++) acc[i][j] += av[i] * bv[j];
        }
        __syncthreads();
    }

    // --- epilogue ---
    const float SQRT2 = 1.41421356237309515f;
    float* outb = out + (size_t)b * out_bstride;
    float nwv = (EPI == 1) ? nwp[0] : 0.f;
#pragma unroll
    for (int i = 0; i < 8; i++) {
        int co   = co0 + ty8 + i;
        float dm = dmod[b * 512 + co];
        float bi = (EPI == 1) ? bias[co] : 0.f;
        float sn = (EPI == 1) ? snext[b * 512 + co] : 0.f;
#pragma unroll
        for (int j = 0; j < 8; j++) {
            int n = n0 + tx8 + j;
            if (n < GHW) {
                int oy = n / GW;
                int ox = n - oy * GW;
                float v = acc[i][j] * dm;
                if (EPI == 1) {
                    v += nwv * noise[b * GHW + n] + bi;
                    v = (v >= 0.f ? v : 0.2f * v) * SQRT2;
                    v *= sn;
                }
                outb[(size_t)co * out_cstride + oy * out_ys + ox * out_xs + out_off] = v;
            }
        }
    }
}

// ---------------- K2: blur 4x4 + noise + bias + lrelu + s2 fold -------------
__global__ void k_blur(const float* __restrict__ t1, const float* __restrict__ n1,
                       const float* __restrict__ nw1, const float* __restrict__ b1,
                       const float* __restrict__ s2, float* __restrict__ a1) {
    int pix = blockIdx.x * 256 + threadIdx.x;  // 0..4095
    int c = blockIdx.y, b = blockIdx.z;
    int y = pix >> 6, x = pix & 63;
    const float kv[4] = {1.f, 3.f, 3.f, 1.f};
    const float* tb = t1 + (size_t)(b * 512 + c) * (HT * HT);
    float acc = 0.f;
#pragma unroll
    for (int p = 0; p < 4; p++) {
        int ty = y + p - 1;
        if (ty < 0 || ty >= HT) continue;
        float row = 0.f;
#pragma unroll
        for (int q = 0; q < 4; q++) {
            int tx = x + q - 1;
            if (tx < 0 || tx >= HT) continue;
            row += tb[ty * HT + tx] * kv[q];   // kernel symmetric: kv[3-q]==kv[q]
        }
        acc += row * kv[p];
    }
    acc *= (1.f / 16.f);                       // 4*k2 = outer(kv,kv)/16
    float v = acc + nw1[0] * n1[b * 4096 + pix] + b1[c];
    v = (v >= 0.f ? v : 0.2f * v) * 1.41421356237309515f;
    a1[(size_t)(b * 512 + c) * 4096 + pix] = v * s2[b * 512 + c];
}

// ---------------- K4: ToRGB (1x1, no demod) + bias + skip upfirdn up=2 ------
__global__ void k_torgb(const float* __restrict__ a2, const float* __restrict__ wrgb,
                        const float* __restrict__ brgb, const float* __restrict__ skip,
                        float* __restrict__ outp) {
    __shared__ float sw[1536];
    int tid = threadIdx.x;
    int b = blockIdx.y;
    const float srgb = 0.044194173824159216f;  // 1/sqrt(512)
    for (int i = tid; i < 1536; i += 256) sw[i] = wrgb[i] * srgb;
    __syncthreads();

    int pix = blockIdx.x * 256 + tid;
    int y = pix >> 6, x = pix & 63;
    float acc0 = 0.f, acc1 = 0.f, acc2 = 0.f;
    const float* ab = a2 + (size_t)b * 512 * 4096 + pix;
    for (int c = 0; c < 512; c++) {
        float v = ab[(size_t)c * 4096];
        acc0 += sw[c] * v;
        acc1 += sw[512 + c] * v;
        acc2 += sw[1024 + c] * v;
    }

    // skip upsample taps: per-axis two taps derived from upfirdn2d(up=2, pad=(2,2))
    int iy0, iy1, ix0, ix1;
    float wy0, wy1, wx0, wx1;
    if ((y & 1) == 0) { iy0 = y / 2 - 1; wy0 = 1.f; iy1 = y / 2;       wy1 = 3.f; }
    else              { iy0 = (y - 1) / 2; wy0 = 3.f; iy1 = (y + 1) / 2; wy1 = 1.f; }
    if ((x & 1) == 0) { ix0 = x / 2 - 1; wx0 = 1.f; ix1 = x / 2;       wx1 = 3.f; }
    else              { ix0 = (x - 1) / 2; wx0 = 3.f; ix1 = (x + 1) / 2; wx1 = 1.f; }

    float accs[3] = {acc0, acc1, acc2};
#pragma unroll
    for (int o = 0; o < 3; o++) {
        const float* sb = skip + (size_t)(b * 3 + o) * 1024;
        float s = 0.f;
        if (iy0 >= 0 && iy0 < 32) {
            if (ix0 >= 0 && ix0 < 32) s += sb[iy0 * 32 + ix0] * wy0 * wx0;
            if (ix1 >= 0 && ix1 < 32) s += sb[iy0 * 32 + ix1] * wy0 * wx1;
        }
        if (iy1 >= 0 && iy1 < 32) {
            if (ix0 >= 0 && ix0 < 32) s += sb[iy1 * 32 + ix0] * wy1 * wx0;
            if (ix1 >= 0 && ix1 < 32) s += sb[iy1 * 32 + ix1] * wy1 * wx1;
        }
        s *= (1.f / 16.f);
        outp[(size_t)(b * 3 + o) * 4096 + pix] = accs[o] + brgb[o] + s;
    }
}

// ---------------- launch -----------------------------------------------------
extern "C" void kernel_launch(void* const* d_in, const int* in_sizes, int n_in,
                              void* d_out, int out_size) {
    const float* x    = (const float*)d_in[0];
    const float* skip = (const float*)d_in[1];
    const float* w1   = (const float*)d_in[2];
    const float* b1   = (const float*)d_in[3];
    const float* s1   = (const float*)d_in[4];
    const float* nw1  = (const float*)d_in[5];
    const float* n1   = (const float*)d_in[6];
    const float* w2   = (const float*)d_in[7];
    const float* b2   = (const float*)d_in[8];
    const float* s2   = (const float*)d_in[9];
    const float* nw2  = (const float*)d_in[10];
    const float* n2   = (const float*)d_in[11];
    const float* wrgb = (const float*)d_in[12];
    const float* brgb = (const float*)d_in[13];
    const float* srgb = (const float*)d_in[14];
    float* outp = (float*)d_out;

    float *xs, *t1, *a1, *a2, *d1, *d2;
    cudaGetSymbolAddress((void**)&xs, g_xs);
    cudaGetSymbolAddress((void**)&t1, g_t1);
    cudaGetSymbolAddress((void**)&a1, g_a1);
    cudaGetSymbolAddress((void**)&a2, g_a2);
    cudaGetSymbolAddress((void**)&d1, g_d1);
    cudaGetSymbolAddress((void**)&d2, g_d2);

    const float sc = 1.0f / sqrtf(512.0f * 9.0f);

    k_scale_x<<<(NB * NC * HIN * HIN + 255) / 256, 256>>>(x, s1, xs);
    k_demod<<<NB * NC, 128>>>(w1, s1, d1, sc);
    k_demod<<<NB * NC, 128>>>(w2, s2, d2, sc);

    // conv1 = conv_transpose(stride 2) split into 4 parity phases.
    // phase(ey,ex): out_t[2m+ey, 2n+ex] = sum_{taps} xs[m+dy, n+dx] * w1[.,., wo]
    int bstride1 = NC * HT * HT;

    {   // phase (0,0): 4 taps, grid 33x33
        TapList tp = {{0, 0, -1, -1, 0, 0, 0, 0, 0},
                      {0, -1, 0, -1, 0, 0, 0, 0, 0},
                      {0, 2, 6, 8, 0, 0, 0, 0, 0}};
        conv_gemm<4, 0><<<dim3((33 * 33 + 127) / 128, 4, NB), 256>>>(
            xs, w1, t1, d1, nullptr, nullptr, nullptr, nullptr,
            HIN, HIN, 33, 33, bstride1, HT * HT, 2 * HT, 2, 0 * HT + 0, tp);
    }
    {   // phase (0,1): 2 taps, grid 33x32
        TapList tp = {{0, -1, 0, 0, 0, 0, 0, 0, 0},
                      {0, 0, 0, 0, 0, 0, 0, 0, 0},
                      {1, 7, 0, 0, 0, 0, 0, 0, 0}};
        conv_gemm<2, 0><<<dim3((33 * 32 + 127) / 128, 4, NB), 256>>>(
            xs, w1, t1, d1, nullptr, nullptr, nullptr, nullptr,
            HIN, HIN, 33, 32, bstride1, HT * HT, 2 * HT, 2, 0 * HT + 1, tp);
    }
    {   // phase (1,0): 2 taps, grid 32x33
        TapList tp = {{0, 0, 0, 0, 0, 0, 0, 0, 0},
                      {0, -1, 0, 0, 0, 0, 0, 0, 0},
                      {3, 5, 0, 0, 0, 0, 0, 0, 0}};
        conv_gemm<2, 0><<<dim3((32 * 33 + 127) / 128, 4, NB), 256>>>(
            xs, w1, t1, d1, nullptr, nullptr, nullptr, nullptr,
            HIN, HIN, 32, 33, bstride1, HT * HT, 2 * HT, 2, 1 * HT + 0, tp);
    }
    {   // phase (1,1): 1 tap, grid 32x32
        TapList tp = {{0, 0, 0, 0, 0, 0, 0, 0, 0},
                      {0, 0, 0, 0, 0, 0, 0, 0, 0},
                      {4, 0, 0, 0, 0, 0, 0, 0, 0}};
        conv_gemm<1, 0><<<dim3((32 * 32 + 127) / 128, 4, NB), 256>>>(
            xs, w1, t1, d1, nullptr, nullptr, nullptr, nullptr,
            HIN, HIN, 32, 32, bstride1, HT * HT, 2 * HT, 2, 1 * HT + 1, tp);
    }

    k_blur<<<dim3(16, NC, NB), 256>>>(t1, n1, nw1, b1, s2, a1);

    {   // conv2: 3x3 same, 9 taps
        TapList tp = {{-1, -1, -1, 0, 0, 0, 1, 1, 1},
                      {-1, 0, 1, -1, 0, 1, -1, 0, 1},
                      {0, 1, 2, 3, 4, 5, 6, 7, 8}};
        conv_gemm<9, 1><<<dim3((HO * HO + 127) / 128, 4, NB), 256>>>(
            a1, w2, a2, d2, n2, nw2, b2, srgb,
            HO, HO, HO, HO, NC * HO * HO, HO * HO, HO, 1, 0, tp);
    }

    k_torgb<<<dim3(16, NB), 256>>>(a2, wrgb, brgb, skip, outp);
}